// round 1
// baseline (speedup 1.0000x reference)
#include <cuda_runtime.h>
#include <math.h>

#define Bb   8
#define Nn   1024
#define INc  256
#define AXc  512
#define Dd   768
#define OUTc 256
#define ALPHA 0.2f
#define NEGV  -9.0e15f

// ---------------- scratch (static device globals; no allocation) ----------------
__device__ float g_M[OUTc * INc];        // fc_w[:, :256] @ WQ_w   (256x256)
__device__ float g_v1[INc], g_v2[INc];   // WQ^T @ a1a, WQ^T @ a2a
__device__ float g_zb[OUTc];             // WQ_b @ W1^T
__device__ float g_c[2];                 // WQ_b . a1a, WQ_b . a2a
__device__ float g_f1[Bb * Nn], g_f2[Bb * Nn];
__device__ float g_att[(size_t)Bb * Nn * Nn];   // 32 MB softmax weights
__device__ float g_z[(size_t)Bb * Nn * OUTc];   // 8 MB  z = h @ fc_w^T

// ---------------- prep: fold WQ into fc_w and a ----------------
__global__ void prep_M(const float* __restrict__ fc_w, const float* __restrict__ WQ) {
    int o = blockIdx.x;      // 0..255
    int k = threadIdx.x;     // 0..255
    const float* fr = fc_w + o * Dd;
    float s = 0.f;
    for (int t = 0; t < INc; ++t)
        s += fr[t] * WQ[t * INc + k];
    g_M[o * INc + k] = s;
}

__global__ void prep_small(const float* __restrict__ WQ, const float* __restrict__ WQb,
                           const float* __restrict__ a, const float* __restrict__ fc_w) {
    int t = threadIdx.x;     // 0..255
    float s1 = 0.f, s2 = 0.f;
    for (int r = 0; r < INc; ++r) {
        float w = WQ[r * INc + t];
        s1 += w * a[r];
        s2 += w * a[Dd + r];
    }
    g_v1[t] = s1;
    g_v2[t] = s2;
    const float* fr = fc_w + t * Dd;
    float z = 0.f;
    for (int r = 0; r < INc; ++r) z += WQb[r] * fr[r];
    g_zb[t] = z;
    __shared__ float r1[256], r2[256];
    r1[t] = WQb[t] * a[t];
    r2[t] = WQb[t] * a[Dd + t];
    __syncthreads();
    for (int st = 128; st > 0; st >>= 1) {
        if (t < st) { r1[t] += r1[t + st]; r2[t] += r2[t + st]; }
        __syncthreads();
    }
    if (t == 0) { g_c[0] = r1[0]; g_c[1] = r2[0]; }
}

// ---------------- f1/f2: per-node attention logits ----------------
// f1[b,n] = sum_k x[b,k,n]*v1[k] + sum_c ax[b,c,n]*a[256+c] + c1    (f2 analogous)
__global__ void f_kernel(const float* __restrict__ x, const float* __restrict__ ax,
                         const float* __restrict__ a) {
    int b  = blockIdx.y;
    int n  = blockIdx.x * 32 + threadIdx.x;
    int ty = threadIdx.y;  // 0..7
    const float* xb  = x  + (size_t)b * INc * Nn;
    const float* axb = ax + (size_t)b * AXc * Nn;
    float s1 = 0.f, s2 = 0.f;
    for (int k = ty; k < INc; k += 8) {
        float v = xb[k * Nn + n];
        s1 += v * g_v1[k];
        s2 += v * g_v2[k];
    }
    for (int c = ty; c < AXc; c += 8) {
        float v = axb[c * Nn + n];
        s1 += v * a[INc + c];
        s2 += v * a[Dd + INc + c];
    }
    __shared__ float r1[8][32], r2[8][32];
    r1[ty][threadIdx.x] = s1;
    r2[ty][threadIdx.x] = s2;
    __syncthreads();
    if (ty == 0) {
        float t1 = 0.f, t2 = 0.f;
        #pragma unroll
        for (int u = 0; u < 8; ++u) { t1 += r1[u][threadIdx.x]; t2 += r2[u][threadIdx.x]; }
        g_f1[b * Nn + n] = t1 + g_c[0];
        g_f2[b * Nn + n] = t2 + g_c[1];
    }
}

// ---------------- masked softmax rows ----------------
__global__ void att_kernel(const int* __restrict__ adj) {
    int b = blockIdx.y, i = blockIdx.x;
    int t = threadIdx.x;  // 256
    __shared__ float sv[Nn];
    __shared__ float red[256];
    float f1v = g_f1[b * Nn + i];
    const int*   arow = adj + ((size_t)b * Nn + i) * Nn;
    const float* f2r  = g_f2 + b * Nn;
    float m = -3.4e38f;
    for (int j = t; j < Nn; j += 256) {
        float v = f1v + f2r[j];
        v = v > 0.f ? v : ALPHA * v;           // leaky_relu
        v = (arow[j] > 0) ? v : NEGV;          // mask
        sv[j] = v;
        m = fmaxf(m, v);
    }
    red[t] = m; __syncthreads();
    for (int st = 128; st > 0; st >>= 1) {
        if (t < st) red[t] = fmaxf(red[t], red[t + st]);
        __syncthreads();
    }
    m = red[0]; __syncthreads();
    float s = 0.f;
    for (int j = t; j < Nn; j += 256) {
        float p = __expf(sv[j] - m);
        sv[j] = p;
        s += p;
    }
    red[t] = s; __syncthreads();
    for (int st = 128; st > 0; st >>= 1) {
        if (t < st) red[t] += red[t + st];
        __syncthreads();
    }
    float inv = 1.f / red[0];
    float* orow = g_att + ((size_t)b * Nn + i) * Nn;
    for (int j = t; j < Nn; j += 256) orow[j] = sv[j] * inv;
}

// ---------------- z = [x;ax]^T @ Wcat^T + zb  (Wcat = [M | fc_w[:,256:]]) ----------------
#define TBK 16
__global__ void z_gemm(const float* __restrict__ x, const float* __restrict__ ax,
                       const float* __restrict__ fc_w) {
    int b  = blockIdx.z;
    int n0 = blockIdx.y * 64;
    int o0 = blockIdx.x * 64;
    const float* xb  = x  + (size_t)b * INc * Nn;
    const float* axb = ax + (size_t)b * AXc * Nn;
    __shared__ float As[TBK][64];       // [k][n]
    __shared__ float Ws[TBK][68];       // [k][o], padded for 16B-aligned rows
    int t  = threadIdx.x;
    int tx = t & 15, ty = t >> 4;
    float acc[4][4];
    #pragma unroll
    for (int i = 0; i < 4; ++i)
        #pragma unroll
        for (int j = 0; j < 4; ++j) acc[i][j] = 0.f;

    for (int k0 = 0; k0 < Dd; k0 += TBK) {
        #pragma unroll
        for (int r = 0; r < 4; ++r) {          // A tile: 16k x 64n, coalesced on n
            int idx = r * 256 + t;
            int kk = idx >> 6, nn = idx & 63;
            int kg = k0 + kk;
            As[kk][nn] = (kg < INc) ? xb[kg * Nn + n0 + nn]
                                    : axb[(kg - INc) * Nn + n0 + nn];
        }
        #pragma unroll
        for (int r = 0; r < 4; ++r) {          // W tile: 64o x 16k -> transposed store
            int idx = r * 256 + t;
            int oo = idx >> 4, kk = idx & 15;
            int kg = k0 + kk;
            Ws[kk][oo] = (kg < INc) ? g_M[(o0 + oo) * INc + kg]
                                    : fc_w[(o0 + oo) * Dd + kg];
        }
        __syncthreads();
        #pragma unroll
        for (int kk = 0; kk < TBK; ++kk) {
            float4 va = *(const float4*)&As[kk][ty * 4];
            float4 vb = *(const float4*)&Ws[kk][tx * 4];
            float ra[4] = {va.x, va.y, va.z, va.w};
            float rb[4] = {vb.x, vb.y, vb.z, vb.w};
            #pragma unroll
            for (int i = 0; i < 4; ++i)
                #pragma unroll
                for (int j = 0; j < 4; ++j) acc[i][j] += ra[i] * rb[j];
        }
        __syncthreads();
    }
    #pragma unroll
    for (int i = 0; i < 4; ++i) {
        int n = n0 + ty * 4 + i;
        int ob = o0 + tx * 4;
        float4 v;
        v.x = acc[i][0] + g_zb[ob + 0];
        v.y = acc[i][1] + g_zb[ob + 1];
        v.z = acc[i][2] + g_zb[ob + 2];
        v.w = acc[i][3] + g_zb[ob + 3];
        *(float4*)(g_z + ((size_t)b * Nn + n) * OUTc + ob) = v;
    }
}

// ---------------- out = elu(att @ z + fc_b) ----------------
__global__ void out_gemm(const float* __restrict__ fc_b, float* __restrict__ out) {
    int b  = blockIdx.z;
    int i0 = blockIdx.y * 64;
    int o0 = blockIdx.x * 64;
    const float* A = g_att + (size_t)b * Nn * Nn;
    const float* Z = g_z   + (size_t)b * Nn * OUTc;
    __shared__ float As[TBK][68];       // [k][i], transposed store, padded
    __shared__ float Bs[TBK][64];       // [k][o]
    int t  = threadIdx.x;
    int tx = t & 15, ty = t >> 4;
    float acc[4][4];
    #pragma unroll
    for (int i = 0; i < 4; ++i)
        #pragma unroll
        for (int j = 0; j < 4; ++j) acc[i][j] = 0.f;

    for (int k0 = 0; k0 < Nn; k0 += TBK) {
        #pragma unroll
        for (int r = 0; r < 4; ++r) {          // att tile: 64i x 16k -> transposed
            int idx = r * 256 + t;
            int ii = idx >> 4, kk = idx & 15;
            As[kk][ii] = A[(size_t)(i0 + ii) * Nn + k0 + kk];
        }
        #pragma unroll
        for (int r = 0; r < 4; ++r) {          // z tile: 16k x 64o, coalesced on o
            int idx = r * 256 + t;
            int kk = idx >> 6, oo = idx & 63;
            Bs[kk][oo] = Z[(k0 + kk) * OUTc + o0 + oo];
        }
        __syncthreads();
        #pragma unroll
        for (int kk = 0; kk < TBK; ++kk) {
            float4 va = *(const float4*)&As[kk][ty * 4];
            float4 vb = *(const float4*)&Bs[kk][tx * 4];
            float ra[4] = {va.x, va.y, va.z, va.w};
            float rb[4] = {vb.x, vb.y, vb.z, vb.w};
            #pragma unroll
            for (int i = 0; i < 4; ++i)
                #pragma unroll
                for (int j = 0; j < 4; ++j) acc[i][j] += ra[i] * rb[j];
        }
        __syncthreads();
    }
    #pragma unroll
    for (int i = 0; i < 4; ++i) {
        int ii = i0 + ty * 4 + i;
        #pragma unroll
        for (int j = 0; j < 4; ++j) {
            int o = o0 + tx * 4 + j;
            float v = acc[i][j] + fc_b[o];
            v = v > 0.f ? v : (__expf(v) - 1.f);   // elu
            out[((size_t)b * Nn + ii) * OUTc + o] = v;
        }
    }
}

extern "C" void kernel_launch(void* const* d_in, const int* in_sizes, int n_in,
                              void* d_out, int out_size) {
    const float* x    = (const float*)d_in[0];
    const float* ax   = (const float*)d_in[1];
    const int*   adj  = (const int*)d_in[2];
    const float* WQ_w = (const float*)d_in[3];
    const float* WQ_b = (const float*)d_in[4];
    const float* a    = (const float*)d_in[5];
    const float* fc_w = (const float*)d_in[6];
    const float* fc_b = (const float*)d_in[7];
    float* out = (float*)d_out;

    prep_M<<<256, 256>>>(fc_w, WQ_w);
    prep_small<<<1, 256>>>(WQ_w, WQ_b, a, fc_w);

    dim3 fg(Nn / 32, Bb), fb(32, 8);
    f_kernel<<<fg, fb>>>(x, ax, a);

    dim3 ag(Nn, Bb);
    att_kernel<<<ag, 256>>>(adj);

    dim3 zg(OUTc / 64, Nn / 64, Bb);
    z_gemm<<<zg, 256>>>(x, ax, fc_w);

    dim3 og(OUTc / 64, Nn / 64, Bb);
    out_gemm<<<og, 256>>>(fc_b, out);
}

// round 5
// speedup vs baseline: 1.5870x; 1.5870x over previous
#include <cuda_runtime.h>
#include <cuda_bf16.h>
#include <stdint.h>
#include <math.h>

#define Bb   8
#define Nn   1024
#define INc  256
#define AXc  512
#define Dd   768
#define OUTc 256
#define ALPHA 0.2f
#define NEGV  -9.0e15f

typedef __nv_bfloat16 bf16;

// ---------------- scratch (static device globals; no allocation) ----------------
__device__ float g_M[OUTc * INc];        // fc_w[:, :256] @ WQ_w
__device__ float g_v1[INc], g_v2[INc];
__device__ float g_zb[OUTc];
__device__ float g_c[2];
__device__ float g_f1[Bb * Nn], g_f2[Bb * Nn];

__device__ __align__(16) bf16 g_att_h[(size_t)Bb * Nn * Nn];   // att hi/lo, [b][i][j]
__device__ __align__(16) bf16 g_att_l[(size_t)Bb * Nn * Nn];
__device__ __align__(16) bf16 g_X_h[(size_t)Bb * Nn * Dd];     // Xcat^T, [b][n][k]
__device__ __align__(16) bf16 g_X_l[(size_t)Bb * Nn * Dd];
__device__ __align__(16) bf16 g_W_h[OUTc * Dd];                // Wcat, [o][k]
__device__ __align__(16) bf16 g_W_l[OUTc * Dd];
__device__ __align__(16) bf16 g_z_h[(size_t)Bb * OUTc * Nn];   // z^T,  [b][o][n]
__device__ __align__(16) bf16 g_z_l[(size_t)Bb * OUTc * Nn];

__device__ __forceinline__ void split_bf16(float v, bf16& h, bf16& l) {
    h = __float2bfloat16(v);
    l = __float2bfloat16(v - __bfloat162float(h));
}

__device__ __forceinline__ void ldsm4(uint32_t& r0, uint32_t& r1, uint32_t& r2,
                                      uint32_t& r3, uint32_t addr) {
    asm volatile(
        "ldmatrix.sync.aligned.m8n8.x4.shared.b16 {%0,%1,%2,%3}, [%4];"
        : "=r"(r0), "=r"(r1), "=r"(r2), "=r"(r3) : "r"(addr));
}

__device__ __forceinline__ void mma16816(float& c0, float& c1, float& c2, float& c3,
                                         uint32_t a0, uint32_t a1, uint32_t a2, uint32_t a3,
                                         uint32_t b0, uint32_t b1) {
    asm volatile(
        "mma.sync.aligned.m16n8k16.row.col.f32.bf16.bf16.f32 "
        "{%0,%1,%2,%3},{%4,%5,%6,%7},{%8,%9},{%0,%1,%2,%3};"
        : "+f"(c0), "+f"(c1), "+f"(c2), "+f"(c3)
        : "r"(a0), "r"(a1), "r"(a2), "r"(a3), "r"(b0), "r"(b1));
}

// ---------------- prep ----------------
__global__ void prep_M(const float* __restrict__ fc_w, const float* __restrict__ WQ) {
    int o = blockIdx.x, k = threadIdx.x;
    const float* fr = fc_w + o * Dd;
    float s = 0.f;
    for (int t = 0; t < INc; ++t) s += fr[t] * WQ[t * INc + k];
    g_M[o * INc + k] = s;
}

__global__ void prep_small(const float* __restrict__ WQ, const float* __restrict__ WQb,
                           const float* __restrict__ a, const float* __restrict__ fc_w) {
    int t = threadIdx.x;
    float s1 = 0.f, s2 = 0.f;
    for (int r = 0; r < INc; ++r) {
        float w = WQ[r * INc + t];
        s1 += w * a[r];
        s2 += w * a[Dd + r];
    }
    g_v1[t] = s1; g_v2[t] = s2;
    const float* fr = fc_w + t * Dd;
    float z = 0.f;
    for (int r = 0; r < INc; ++r) z += WQb[r] * fr[r];
    g_zb[t] = z;
    __shared__ float r1[256], r2[256];
    r1[t] = WQb[t] * a[t];
    r2[t] = WQb[t] * a[Dd + t];
    __syncthreads();
    for (int st = 128; st > 0; st >>= 1) {
        if (t < st) { r1[t] += r1[t + st]; r2[t] += r2[t + st]; }
        __syncthreads();
    }
    if (t == 0) { g_c[0] = r1[0]; g_c[1] = r2[0]; }
}

__global__ void conv_w(const float* __restrict__ fc_w) {
    int idx = blockIdx.x * 256 + threadIdx.x;
    int o = idx / Dd, k = idx - o * Dd;
    float v = (k < INc) ? g_M[o * INc + k] : fc_w[o * Dd + k];
    bf16 h, l; split_bf16(v, h, l);
    g_W_h[idx] = h; g_W_l[idx] = l;
}

__global__ void conv_x(const float* __restrict__ x, const float* __restrict__ ax) {
    __shared__ float tile[32][33];
    int b = blockIdx.z;
    int k0 = blockIdx.x * 32, n0 = blockIdx.y * 32;
    int tx = threadIdx.x, ty = threadIdx.y;
    int kk = k0 + ty, nn = n0 + tx;
    float v = (kk < INc) ? x[((size_t)b * INc + kk) * Nn + nn]
                         : ax[((size_t)b * AXc + (kk - INc)) * Nn + nn];
    tile[ty][tx] = v;
    __syncthreads();
    int on = n0 + ty, ok = k0 + tx;
    float w = tile[tx][ty];
    bf16 h, l; split_bf16(w, h, l);
    size_t idx = ((size_t)b * Nn + on) * Dd + ok;
    g_X_h[idx] = h; g_X_l[idx] = l;
}

// ---------------- f1/f2 ----------------
__global__ void f_kernel(const float* __restrict__ x, const float* __restrict__ ax,
                         const float* __restrict__ a) {
    int b  = blockIdx.y;
    int n  = blockIdx.x * 32 + threadIdx.x;
    int ty = threadIdx.y;
    const float* xb  = x  + (size_t)b * INc * Nn;
    const float* axb = ax + (size_t)b * AXc * Nn;
    float s1 = 0.f, s2 = 0.f;
    for (int k = ty; k < INc; k += 8) {
        float v = xb[k * Nn + n];
        s1 += v * g_v1[k];
        s2 += v * g_v2[k];
    }
    for (int c = ty; c < AXc; c += 8) {
        float v = axb[c * Nn + n];
        s1 += v * a[INc + c];
        s2 += v * a[Dd + INc + c];
    }
    __shared__ float r1[8][32], r2[8][32];
    r1[ty][threadIdx.x] = s1;
    r2[ty][threadIdx.x] = s2;
    __syncthreads();
    if (ty == 0) {
        float t1 = 0.f, t2 = 0.f;
        #pragma unroll
        for (int u = 0; u < 8; ++u) { t1 += r1[u][threadIdx.x]; t2 += r2[u][threadIdx.x]; }
        g_f1[b * Nn + n] = t1 + g_c[0];
        g_f2[b * Nn + n] = t2 + g_c[1];
    }
}

// ---------------- masked softmax rows -> bf16 hi/lo ----------------
__global__ void att_kernel(const int* __restrict__ adj) {
    int b = blockIdx.y, i = blockIdx.x;
    int t = threadIdx.x;
    __shared__ float sv[Nn];
    __shared__ float red[256];
    float f1v = g_f1[b * Nn + i];
    const int*   arow = adj + ((size_t)b * Nn + i) * Nn;
    const float* f2r  = g_f2 + b * Nn;
    float m = -3.4e38f;
    for (int j = t; j < Nn; j += 256) {
        float v = f1v + f2r[j];
        v = v > 0.f ? v : ALPHA * v;
        v = (arow[j] > 0) ? v : NEGV;
        sv[j] = v;
        m = fmaxf(m, v);
    }
    red[t] = m; __syncthreads();
    for (int st = 128; st > 0; st >>= 1) {
        if (t < st) red[t] = fmaxf(red[t], red[t + st]);
        __syncthreads();
    }
    m = red[0]; __syncthreads();
    float s = 0.f;
    for (int j = t; j < Nn; j += 256) {
        float p = __expf(sv[j] - m);
        sv[j] = p;
        s += p;
    }
    red[t] = s; __syncthreads();
    for (int st = 128; st > 0; st >>= 1) {
        if (t < st) red[t] += red[t + st];
        __syncthreads();
    }
    float inv = 1.f / red[0];
    size_t base = ((size_t)b * Nn + i) * Nn;
    for (int j = t; j < Nn; j += 256) {
        float p = sv[j] * inv;
        bf16 h, l; split_bf16(p, h, l);
        g_att_h[base + j] = h;
        g_att_l[base + j] = l;
    }
}

// ---------------- tensor-core GEMMs (no templates, duplicated bodies) ----------------
#define SROW 24   // smem row length in halves (48B -> conflict-free LDSM)

// z^T[o][n] = Wcat @ Xcat^T : M=256(o), N=1024(n), K=768
__global__ __launch_bounds__(256) void z_mma() {
    const int K = Dd;
    int b  = blockIdx.z;
    int m0 = blockIdx.y * 128;
    int n0 = blockIdx.x * 128;
    const bf16* Ah = g_W_h;
    const bf16* Al = g_W_l;
    const bf16* Bh = g_X_h + (size_t)b * Nn * Dd;
    const bf16* Bl = g_X_l + (size_t)b * Nn * Dd;

    __shared__ __align__(16) bf16 sAh[128 * SROW], sAl[128 * SROW];
    __shared__ __align__(16) bf16 sBh[128 * SROW], sBl[128 * SROW];

    int t = threadIdx.x;
    int lrow = t >> 1, lhalf = t & 1;
    const bf16* pAh = Ah + (size_t)(m0 + lrow) * K + lhalf * 8;
    const bf16* pAl = Al + (size_t)(m0 + lrow) * K + lhalf * 8;
    const bf16* pBh = Bh + (size_t)(n0 + lrow) * K + lhalf * 8;
    const bf16* pBl = Bl + (size_t)(n0 + lrow) * K + lhalf * 8;
    int sidx = lrow * 3 + lhalf;

    int wid = t >> 5, lane = t & 31;
    int wm0 = (wid >> 2) * 64;
    int wn0 = (wid & 3) * 32;
    int lr = lane & 15, lc = (lane >> 4) * 8;

    uint32_t saAh = (uint32_t)__cvta_generic_to_shared(sAh);
    uint32_t saAl = (uint32_t)__cvta_generic_to_shared(sAl);
    uint32_t saBh = (uint32_t)__cvta_generic_to_shared(sBh);
    uint32_t saBl = (uint32_t)__cvta_generic_to_shared(sBl);
    uint32_t aAddrH[4], aAddrL[4], bAddrH[2], bAddrL[2];
    #pragma unroll
    for (int mb = 0; mb < 4; ++mb) {
        uint32_t off = (uint32_t)((wm0 + mb * 16 + lr) * SROW + lc) * 2;
        aAddrH[mb] = saAh + off;
        aAddrL[mb] = saAl + off;
    }
    #pragma unroll
    for (int g = 0; g < 2; ++g) {
        uint32_t off = (uint32_t)((wn0 + g * 16 + lr) * SROW + lc) * 2;
        bAddrH[g] = saBh + off;
        bAddrL[g] = saBl + off;
    }

    float acc[4][4][4];
    #pragma unroll
    for (int i = 0; i < 4; ++i)
        #pragma unroll
        for (int j = 0; j < 4; ++j)
            #pragma unroll
            for (int q = 0; q < 4; ++q) acc[i][j][q] = 0.f;

    uint4 fa  = *(const uint4*)pAh;
    uint4 fb  = *(const uint4*)pAl;
    uint4 fc4 = *(const uint4*)pBh;
    uint4 fd  = *(const uint4*)pBl;

    uint32_t Afh[4][4], Afl[4][4], Bfh[2][4], Bfl[2][4];

    for (int k0 = 0; k0 < K; k0 += 16) {
        ((uint4*)sAh)[sidx] = fa;
        ((uint4*)sAl)[sidx] = fb;
        ((uint4*)sBh)[sidx] = fc4;
        ((uint4*)sBl)[sidx] = fd;
        __syncthreads();
        if (k0 + 16 < K) {
            fa  = *(const uint4*)(pAh + k0 + 16);
            fb  = *(const uint4*)(pAl + k0 + 16);
            fc4 = *(const uint4*)(pBh + k0 + 16);
            fd  = *(const uint4*)(pBl + k0 + 16);
        }
        #pragma unroll
        for (int mb = 0; mb < 4; ++mb) {
            ldsm4(Afh[mb][0], Afh[mb][1], Afh[mb][2], Afh[mb][3], aAddrH[mb]);
            ldsm4(Afl[mb][0], Afl[mb][1], Afl[mb][2], Afl[mb][3], aAddrL[mb]);
        }
        #pragma unroll
        for (int g = 0; g < 2; ++g) {
            ldsm4(Bfh[g][0], Bfh[g][1], Bfh[g][2], Bfh[g][3], bAddrH[g]);
            ldsm4(Bfl[g][0], Bfl[g][1], Bfl[g][2], Bfl[g][3], bAddrL[g]);
        }
        #pragma unroll
        for (int mb = 0; mb < 4; ++mb) {
            #pragma unroll
            for (int j = 0; j < 4; ++j) {
                int g = j >> 1, p = j & 1;
                float* C = acc[mb][j];
                mma16816(C[0], C[1], C[2], C[3],
                         Afh[mb][0], Afh[mb][1], Afh[mb][2], Afh[mb][3],
                         Bfh[g][p], Bfh[g][p + 2]);
                mma16816(C[0], C[1], C[2], C[3],
                         Afh[mb][0], Afh[mb][1], Afh[mb][2], Afh[mb][3],
                         Bfl[g][p], Bfl[g][p + 2]);
                mma16816(C[0], C[1], C[2], C[3],
                         Afl[mb][0], Afl[mb][1], Afl[mb][2], Afl[mb][3],
                         Bfh[g][p], Bfh[g][p + 2]);
            }
        }
        __syncthreads();
    }

    int r_lo = lane >> 2, c_off = (lane & 3) * 2;
    size_t base = (size_t)b * OUTc * Nn;
    #pragma unroll
    for (int mb = 0; mb < 4; ++mb) {
        #pragma unroll
        for (int j = 0; j < 4; ++j) {
            int row = m0 + wm0 + mb * 16 + r_lo;
            int col = n0 + wn0 + j * 8 + c_off;
            float* C = acc[mb][j];
            #pragma unroll
            for (int h = 0; h < 2; ++h) {
                int rr = row + h * 8;
                float bz = g_zb[rr];
                #pragma unroll
                for (int q = 0; q < 2; ++q) {
                    float v = C[h * 2 + q] + bz;
                    bf16 hi, lo; split_bf16(v, hi, lo);
                    size_t idx = base + (size_t)rr * Nn + col + q;
                    g_z_h[idx] = hi; g_z_l[idx] = lo;
                }
            }
        }
    }
}

// out[i][o] = elu(att @ z^T + fc_b) : M=1024(i), N=256(o), K=1024
__global__ __launch_bounds__(256) void out_mma(const float* __restrict__ bias,
                                               float* __restrict__ outF) {
    const int K = Nn;
    int b  = blockIdx.z;
    int m0 = blockIdx.y * 128;
    int n0 = blockIdx.x * 128;
    const bf16* Ah = g_att_h + (size_t)b * Nn * Nn;
    const bf16* Al = g_att_l + (size_t)b * Nn * Nn;
    const bf16* Bh = g_z_h + (size_t)b * OUTc * Nn;
    const bf16* Bl = g_z_l + (size_t)b * OUTc * Nn;

    __shared__ __align__(16) bf16 sAh[128 * SROW], sAl[128 * SROW];
    __shared__ __align__(16) bf16 sBh[128 * SROW], sBl[128 * SROW];

    int t = threadIdx.x;
    int lrow = t >> 1, lhalf = t & 1;
    const bf16* pAh = Ah + (size_t)(m0 + lrow) * K + lhalf * 8;
    const bf16* pAl = Al + (size_t)(m0 + lrow) * K + lhalf * 8;
    const bf16* pBh = Bh + (size_t)(n0 + lrow) * K + lhalf * 8;
    const bf16* pBl = Bl + (size_t)(n0 + lrow) * K + lhalf * 8;
    int sidx = lrow * 3 + lhalf;

    int wid = t >> 5, lane = t & 31;
    int wm0 = (wid >> 2) * 64;
    int wn0 = (wid & 3) * 32;
    int lr = lane & 15, lc = (lane >> 4) * 8;

    uint32_t saAh = (uint32_t)__cvta_generic_to_shared(sAh);
    uint32_t saAl = (uint32_t)__cvta_generic_to_shared(sAl);
    uint32_t saBh = (uint32_t)__cvta_generic_to_shared(sBh);
    uint32_t saBl = (uint32_t)__cvta_generic_to_shared(sBl);
    uint32_t aAddrH[4], aAddrL[4], bAddrH[2], bAddrL[2];
    #pragma unroll
    for (int mb = 0; mb < 4; ++mb) {
        uint32_t off = (uint32_t)((wm0 + mb * 16 + lr) * SROW + lc) * 2;
        aAddrH[mb] = saAh + off;
        aAddrL[mb] = saAl + off;
    }
    #pragma unroll
    for (int g = 0; g < 2; ++g) {
        uint32_t off = (uint32_t)((wn0 + g * 16 + lr) * SROW + lc) * 2;
        bAddrH[g] = saBh + off;
        bAddrL[g] = saBl + off;
    }

    float acc[4][4][4];
    #pragma unroll
    for (int i = 0; i < 4; ++i)
        #pragma unroll
        for (int j = 0; j < 4; ++j)
            #pragma unroll
            for (int q = 0; q < 4; ++q) acc[i][j][q] = 0.f;

    uint4 fa  = *(const uint4*)pAh;
    uint4 fb  = *(const uint4*)pAl;
    uint4 fc4 = *(const uint4*)pBh;
    uint4 fd  = *(const uint4*)pBl;

    uint32_t Afh[4][4], Afl[4][4], Bfh[2][4], Bfl[2][4];

    for (int k0 = 0; k0 < K; k0 += 16) {
        ((uint4*)sAh)[sidx] = fa;
        ((uint4*)sAl)[sidx] = fb;
        ((uint4*)sBh)[sidx] = fc4;
        ((uint4*)sBl)[sidx] = fd;
        __syncthreads();
        if (k0 + 16 < K) {
            fa  = *(const uint4*)(pAh + k0 + 16);
            fb  = *(const uint4*)(pAl + k0 + 16);
            fc4 = *(const uint4*)(pBh + k0 + 16);
            fd  = *(const uint4*)(pBl + k0 + 16);
        }
        #pragma unroll
        for (int mb = 0; mb < 4; ++mb) {
            ldsm4(Afh[mb][0], Afh[mb][1], Afh[mb][2], Afh[mb][3], aAddrH[mb]);
            ldsm4(Afl[mb][0], Afl[mb][1], Afl[mb][2], Afl[mb][3], aAddrL[mb]);
        }
        #pragma unroll
        for (int g = 0; g < 2; ++g) {
            ldsm4(Bfh[g][0], Bfh[g][1], Bfh[g][2], Bfh[g][3], bAddrH[g]);
            ldsm4(Bfl[g][0], Bfl[g][1], Bfl[g][2], Bfl[g][3], bAddrL[g]);
        }
        #pragma unroll
        for (int mb = 0; mb < 4; ++mb) {
            #pragma unroll
            for (int j = 0; j < 4; ++j) {
                int g = j >> 1, p = j & 1;
                float* C = acc[mb][j];
                mma16816(C[0], C[1], C[2], C[3],
                         Afh[mb][0], Afh[mb][1], Afh[mb][2], Afh[mb][3],
                         Bfh[g][p], Bfh[g][p + 2]);
                mma16816(C[0], C[1], C[2], C[3],
                         Afh[mb][0], Afh[mb][1], Afh[mb][2], Afh[mb][3],
                         Bfl[g][p], Bfl[g][p + 2]);
                mma16816(C[0], C[1], C[2], C[3],
                         Afl[mb][0], Afl[mb][1], Afl[mb][2], Afl[mb][3],
                         Bfh[g][p], Bfh[g][p + 2]);
            }
        }
        __syncthreads();
    }

    int r_lo = lane >> 2, c_off = (lane & 3) * 2;
    size_t base = (size_t)b * Nn * OUTc;
    #pragma unroll
    for (int mb = 0; mb < 4; ++mb) {
        #pragma unroll
        for (int j = 0; j < 4; ++j) {
            int row = m0 + wm0 + mb * 16 + r_lo;
            int col = n0 + wn0 + j * 8 + c_off;
            float* C = acc[mb][j];
            #pragma unroll
            for (int h = 0; h < 2; ++h) {
                int rr = row + h * 8;
                #pragma unroll
                for (int q = 0; q < 2; ++q) {
                    float v = C[h * 2 + q] + bias[col + q];
                    v = v > 0.f ? v : (__expf(v) - 1.f);
                    outF[base + (size_t)rr * OUTc + col + q] = v;
                }
            }
        }
    }
}

extern "C" void kernel_launch(void* const* d_in, const int* in_sizes, int n_in,
                              void* d_out, int out_size) {
    const float* x    = (const float*)d_in[0];
    const float* ax   = (const float*)d_in[1];
    const int*   adj  = (const int*)d_in[2];
    const float* WQ_w = (const float*)d_in[3];
    const float* WQ_b = (const float*)d_in[4];
    const float* a    = (const float*)d_in[5];
    const float* fc_w = (const float*)d_in[6];
    const float* fc_b = (const float*)d_in[7];
    float* out = (float*)d_out;

    prep_M<<<256, 256>>>(fc_w, WQ_w);
    prep_small<<<1, 256>>>(WQ_w, WQ_b, a, fc_w);
    conv_w<<<(OUTc * Dd) / 256, 256>>>(fc_w);

    dim3 cxg(Dd / 32, Nn / 32, Bb);
    conv_x<<<cxg, dim3(32, 32)>>>(x, ax);

    dim3 fg(Nn / 32, Bb), fb(32, 8);
    f_kernel<<<fg, fb>>>(x, ax, a);

    dim3 ag(Nn, Bb);
    att_kernel<<<ag, 256>>>(adj);

    z_mma<<<dim3(Nn / 128, OUTc / 128, Bb), 256>>>();
    out_mma<<<dim3(OUTc / 128, Nn / 128, Bb), 256>>>(fc_b, out);
}

// round 6
// speedup vs baseline: 1.9275x; 1.2145x over previous
#include <cuda_runtime.h>
#include <cuda_bf16.h>
#include <stdint.h>
#include <math.h>

#define Bb   8
#define Nn   1024
#define INc  256
#define AXc  512
#define Dd   768
#define OUTc 256
#define ALPHA 0.2f
#define NEGV  -9.0e15f

typedef __nv_bfloat16 bf16;

// ---------------- scratch (static device globals; no allocation) ----------------
__device__ float g_M[OUTc * INc];        // fc_w[:, :256] @ WQ_w
__device__ float g_v1[INc], g_v2[INc];
__device__ float g_zb[OUTc];
__device__ float g_c[2];
__device__ __align__(16) float g_f1[Bb * Nn];
__device__ __align__(16) float g_f2[Bb * Nn];

__device__ __align__(16) bf16 g_att_h[(size_t)Bb * Nn * Nn];   // att hi/lo, [b][i][j]
__device__ __align__(16) bf16 g_att_l[(size_t)Bb * Nn * Nn];
__device__ __align__(16) bf16 g_X_h[(size_t)Bb * Nn * Dd];     // Xcat^T, [b][n][k]
__device__ __align__(16) bf16 g_X_l[(size_t)Bb * Nn * Dd];
__device__ __align__(16) bf16 g_W_h[OUTc * Dd];                // Wcat, [o][k]
__device__ __align__(16) bf16 g_W_l[OUTc * Dd];
__device__ __align__(16) bf16 g_z_h[(size_t)Bb * OUTc * Nn];   // z^T,  [b][o][n]
__device__ __align__(16) bf16 g_z_l[(size_t)Bb * OUTc * Nn];

__device__ __forceinline__ void split_bf16(float v, bf16& h, bf16& l) {
    h = __float2bfloat16(v);
    l = __float2bfloat16(v - __bfloat162float(h));
}

__device__ __forceinline__ uint32_t pack2(bf16 a, bf16 b) {
    return (uint32_t)__bfloat16_as_ushort(a) | ((uint32_t)__bfloat16_as_ushort(b) << 16);
}

__device__ __forceinline__ void ldsm4(uint32_t& r0, uint32_t& r1, uint32_t& r2,
                                      uint32_t& r3, uint32_t addr) {
    asm volatile(
        "ldmatrix.sync.aligned.m8n8.x4.shared.b16 {%0,%1,%2,%3}, [%4];"
        : "=r"(r0), "=r"(r1), "=r"(r2), "=r"(r3) : "r"(addr));
}

__device__ __forceinline__ void mma16816(float& c0, float& c1, float& c2, float& c3,
                                         uint32_t a0, uint32_t a1, uint32_t a2, uint32_t a3,
                                         uint32_t b0, uint32_t b1) {
    asm volatile(
        "mma.sync.aligned.m16n8k16.row.col.f32.bf16.bf16.f32 "
        "{%0,%1,%2,%3},{%4,%5,%6,%7},{%8,%9},{%0,%1,%2,%3};"
        : "+f"(c0), "+f"(c1), "+f"(c2), "+f"(c3)
        : "r"(a0), "r"(a1), "r"(a2), "r"(a3), "r"(b0), "r"(b1));
}

// ---------------- prep ----------------
__global__ void prep_M(const float* __restrict__ fc_w, const float* __restrict__ WQ) {
    int o = blockIdx.x, k = threadIdx.x;
    const float* fr = fc_w + o * Dd;
    float s = 0.f;
    for (int t = 0; t < INc; ++t) s += fr[t] * WQ[t * INc + k];
    g_M[o * INc + k] = s;
}

__global__ void prep_small(const float* __restrict__ WQ, const float* __restrict__ WQb,
                           const float* __restrict__ a, const float* __restrict__ fc_w) {
    int t = threadIdx.x;
    float s1 = 0.f, s2 = 0.f;
    for (int r = 0; r < INc; ++r) {
        float w = WQ[r * INc + t];
        s1 += w * a[r];
        s2 += w * a[Dd + r];
    }
    g_v1[t] = s1; g_v2[t] = s2;
    const float* fr = fc_w + t * Dd;
    float z = 0.f;
    for (int r = 0; r < INc; ++r) z += WQb[r] * fr[r];
    g_zb[t] = z;
    __shared__ float r1[256], r2[256];
    r1[t] = WQb[t] * a[t];
    r2[t] = WQb[t] * a[Dd + t];
    __syncthreads();
    for (int st = 128; st > 0; st >>= 1) {
        if (t < st) { r1[t] += r1[t + st]; r2[t] += r2[t + st]; }
        __syncthreads();
    }
    if (t == 0) { g_c[0] = r1[0]; g_c[1] = r2[0]; }
}

__global__ void conv_w(const float* __restrict__ fc_w) {
    int idx = blockIdx.x * 256 + threadIdx.x;
    int o = idx / Dd, k = idx - o * Dd;
    float v = (k < INc) ? g_M[o * INc + k] : fc_w[o * Dd + k];
    bf16 h, l; split_bf16(v, h, l);
    g_W_h[idx] = h; g_W_l[idx] = l;
}

// Xcat^T: [b][n][k] bf16 hi/lo, tiled transpose, 256 threads, 4 elems/thread
__global__ __launch_bounds__(256) void conv_x(const float* __restrict__ x,
                                              const float* __restrict__ ax) {
    __shared__ float tile[32][33];
    int b = blockIdx.z;
    int k0 = blockIdx.x * 32, n0 = blockIdx.y * 32;
    int t = threadIdx.x;
    int tn = t & 31, tk = t >> 5;   // 8 k-rows per pass
    #pragma unroll
    for (int u = 0; u < 4; ++u) {
        int kk = k0 + tk + 8 * u;
        float vv = (kk < INc) ? x[((size_t)b * INc + kk) * Nn + n0 + tn]
                              : ax[((size_t)b * AXc + (kk - INc)) * Nn + n0 + tn];
        tile[tk + 8 * u][tn] = vv;
    }
    __syncthreads();
    int wn = t >> 3, wk = (t & 7) * 4;
    bf16 h[4], l[4];
    #pragma unroll
    for (int u = 0; u < 4; ++u) split_bf16(tile[wk + u][wn], h[u], l[u]);
    size_t idx = ((size_t)b * Nn + n0 + wn) * Dd + k0 + wk;
    *(uint2*)(g_X_h + idx) = make_uint2(pack2(h[0], h[1]), pack2(h[2], h[3]));
    *(uint2*)(g_X_l + idx) = make_uint2(pack2(l[0], l[1]), pack2(l[2], l[3]));
}

// ---------------- f1/f2 ----------------
__global__ void f_kernel(const float* __restrict__ x, const float* __restrict__ ax,
                         const float* __restrict__ a) {
    int b  = blockIdx.y;
    int n  = blockIdx.x * 32 + threadIdx.x;
    int ty = threadIdx.y;
    const float* xb  = x  + (size_t)b * INc * Nn;
    const float* axb = ax + (size_t)b * AXc * Nn;
    float s1 = 0.f, s2 = 0.f;
    for (int k = ty; k < INc; k += 8) {
        float v = xb[k * Nn + n];
        s1 += v * g_v1[k];
        s2 += v * g_v2[k];
    }
    for (int c = ty; c < AXc; c += 8) {
        float v = axb[c * Nn + n];
        s1 += v * a[INc + c];
        s2 += v * a[Dd + INc + c];
    }
    __shared__ float r1[8][32], r2[8][32];
    r1[ty][threadIdx.x] = s1;
    r2[ty][threadIdx.x] = s2;
    __syncthreads();
    if (ty == 0) {
        float t1 = 0.f, t2 = 0.f;
        #pragma unroll
        for (int u = 0; u < 8; ++u) { t1 += r1[u][threadIdx.x]; t2 += r2[u][threadIdx.x]; }
        g_f1[b * Nn + n] = t1 + g_c[0];
        g_f2[b * Nn + n] = t2 + g_c[1];
    }
}

// ---------------- masked softmax rows -> bf16 hi/lo (register-resident) ----------------
__global__ __launch_bounds__(256) void att_kernel(const int* __restrict__ adj) {
    int b = blockIdx.y, i = blockIdx.x;
    int t = threadIdx.x;
    int lane = t & 31, warp = t >> 5;
    float f1v = g_f1[b * Nn + i];
    const int4*   arow = (const int4*)(adj + ((size_t)b * Nn + i) * Nn);
    const float4* f2r  = (const float4*)(g_f2 + b * Nn);
    float4 f2 = f2r[t];
    int4   ad = arow[t];
    float v[4];
    v[0] = f1v + f2.x; v[1] = f1v + f2.y; v[2] = f1v + f2.z; v[3] = f1v + f2.w;
    #pragma unroll
    for (int q = 0; q < 4; ++q) v[q] = v[q] > 0.f ? v[q] : ALPHA * v[q];
    v[0] = (ad.x > 0) ? v[0] : NEGV;
    v[1] = (ad.y > 0) ? v[1] : NEGV;
    v[2] = (ad.z > 0) ? v[2] : NEGV;
    v[3] = (ad.w > 0) ? v[3] : NEGV;

    float m = fmaxf(fmaxf(v[0], v[1]), fmaxf(v[2], v[3]));
    #pragma unroll
    for (int o = 16; o > 0; o >>= 1) m = fmaxf(m, __shfl_xor_sync(0xffffffffu, m, o));
    __shared__ float redm[8], reds[8];
    if (lane == 0) redm[warp] = m;
    __syncthreads();
    m = redm[0];
    #pragma unroll
    for (int u = 1; u < 8; ++u) m = fmaxf(m, redm[u]);

    float p[4], s = 0.f;
    #pragma unroll
    for (int q = 0; q < 4; ++q) { p[q] = __expf(v[q] - m); s += p[q]; }
    #pragma unroll
    for (int o = 16; o > 0; o >>= 1) s += __shfl_xor_sync(0xffffffffu, s, o);
    if (lane == 0) reds[warp] = s;
    __syncthreads();
    s = reds[0];
    #pragma unroll
    for (int u = 1; u < 8; ++u) s += reds[u];
    float inv = 1.f / s;

    bf16 h[4], l[4];
    #pragma unroll
    for (int q = 0; q < 4; ++q) split_bf16(p[q] * inv, h[q], l[q]);
    size_t base = ((size_t)b * Nn + i) * Nn + t * 4;
    *(uint2*)(g_att_h + base) = make_uint2(pack2(h[0], h[1]), pack2(h[2], h[3]));
    *(uint2*)(g_att_l + base) = make_uint2(pack2(l[0], l[1]), pack2(l[2], l[3]));
}

// ---------------- tensor-core GEMMs, double-buffered ----------------
#define SROW 24            // 48B rows -> conflict-free LDSM, 16B-aligned
#define BUFB (128 * SROW * 2)   // bytes per stage buffer
#define BUFU (128 * 3)          // uint4 slots per stage buffer

// z^T[o][n] = Wcat @ Xcat^T : M=256(o), N=1024(n), K=768
__global__ __launch_bounds__(256) void z_mma() {
    const int K = Dd;
    int b  = blockIdx.z;
    int m0 = blockIdx.y * 128;
    int n0 = blockIdx.x * 128;
    const bf16* Ah = g_W_h;
    const bf16* Al = g_W_l;
    const bf16* Bh = g_X_h + (size_t)b * Nn * Dd;
    const bf16* Bl = g_X_l + (size_t)b * Nn * Dd;

    __shared__ __align__(16) bf16 sAh[2 * 128 * SROW], sAl[2 * 128 * SROW];
    __shared__ __align__(16) bf16 sBh[2 * 128 * SROW], sBl[2 * 128 * SROW];

    int t = threadIdx.x;
    int lrow = t >> 1, lhalf = t & 1;
    const bf16* pAh = Ah + (size_t)(m0 + lrow) * K + lhalf * 8;
    const bf16* pAl = Al + (size_t)(m0 + lrow) * K + lhalf * 8;
    const bf16* pBh = Bh + (size_t)(n0 + lrow) * K + lhalf * 8;
    const bf16* pBl = Bl + (size_t)(n0 + lrow) * K + lhalf * 8;
    int sidx = lrow * 3 + lhalf;

    int wid = t >> 5, lane = t & 31;
    int wm0 = (wid >> 2) * 64;
    int wn0 = (wid & 3) * 32;
    int lr = lane & 15, lc = (lane >> 4) * 8;

    uint32_t saAh = (uint32_t)__cvta_generic_to_shared(sAh);
    uint32_t saAl = (uint32_t)__cvta_generic_to_shared(sAl);
    uint32_t saBh = (uint32_t)__cvta_generic_to_shared(sBh);
    uint32_t saBl = (uint32_t)__cvta_generic_to_shared(sBl);
    uint32_t aAddrH[4], aAddrL[4], bAddrH[2], bAddrL[2];
    #pragma unroll
    for (int mb = 0; mb < 4; ++mb) {
        uint32_t off = (uint32_t)((wm0 + mb * 16 + lr) * SROW + lc) * 2;
        aAddrH[mb] = saAh + off;
        aAddrL[mb] = saAl + off;
    }
    #pragma unroll
    for (int g = 0; g < 2; ++g) {
        uint32_t off = (uint32_t)((wn0 + g * 16 + lr) * SROW + lc) * 2;
        bAddrH[g] = saBh + off;
        bAddrL[g] = saBl + off;
    }

    float acc[4][4][4];
    #pragma unroll
    for (int i = 0; i < 4; ++i)
        #pragma unroll
        for (int j = 0; j < 4; ++j)
            #pragma unroll
            for (int q = 0; q < 4; ++q) acc[i][j][q] = 0.f;

    // prologue: stage 0
    uint4 fa  = *(const uint4*)pAh;
    uint4 fb  = *(const uint4*)pAl;
    uint4 fc4 = *(const uint4*)pBh;
    uint4 fd  = *(const uint4*)pBl;
    ((uint4*)sAh)[sidx] = fa;
    ((uint4*)sAl)[sidx] = fb;
    ((uint4*)sBh)[sidx] = fc4;
    ((uint4*)sBl)[sidx] = fd;
    __syncthreads();

    uint32_t Afh[4][4], Afl[4][4], Bfh[2][4], Bfl[2][4];
    int cur = 0;

    for (int k0 = 0; k0 < K; k0 += 16) {
        bool has_next = (k0 + 16 < K);
        if (has_next) {
            fa  = *(const uint4*)(pAh + k0 + 16);
            fb  = *(const uint4*)(pAl + k0 + 16);
            fc4 = *(const uint4*)(pBh + k0 + 16);
            fd  = *(const uint4*)(pBl + k0 + 16);
        }
        uint32_t co = (uint32_t)cur * BUFB;
        #pragma unroll
        for (int mb = 0; mb < 4; ++mb) {
            ldsm4(Afh[mb][0], Afh[mb][1], Afh[mb][2], Afh[mb][3], aAddrH[mb] + co);
            ldsm4(Afl[mb][0], Afl[mb][1], Afl[mb][2], Afl[mb][3], aAddrL[mb] + co);
        }
        #pragma unroll
        for (int g = 0; g < 2; ++g) {
            ldsm4(Bfh[g][0], Bfh[g][1], Bfh[g][2], Bfh[g][3], bAddrH[g] + co);
            ldsm4(Bfl[g][0], Bfl[g][1], Bfl[g][2], Bfl[g][3], bAddrL[g] + co);
        }
        #pragma unroll
        for (int mb = 0; mb < 4; ++mb) {
            #pragma unroll
            for (int j = 0; j < 4; ++j) {
                int g = j >> 1, p = j & 1;
                float* C = acc[mb][j];
                mma16816(C[0], C[1], C[2], C[3],
                         Afh[mb][0], Afh[mb][1], Afh[mb][2], Afh[mb][3],
                         Bfh[g][p], Bfh[g][p + 2]);
                mma16816(C[0], C[1], C[2], C[3],
                         Afh[mb][0], Afh[mb][1], Afh[mb][2], Afh[mb][3],
                         Bfl[g][p], Bfl[g][p + 2]);
                mma16816(C[0], C[1], C[2], C[3],
                         Afl[mb][0], Afl[mb][1], Afl[mb][2], Afl[mb][3],
                         Bfh[g][p], Bfh[g][p + 2]);
            }
        }
        if (has_next) {
            int nidx = (cur ^ 1) * BUFU + sidx;
            ((uint4*)sAh)[nidx] = fa;
            ((uint4*)sAl)[nidx] = fb;
            ((uint4*)sBh)[nidx] = fc4;
            ((uint4*)sBl)[nidx] = fd;
        }
        __syncthreads();
        cur ^= 1;
    }

    int r_lo = lane >> 2, c_off = (lane & 3) * 2;
    size_t base = (size_t)b * OUTc * Nn;
    #pragma unroll
    for (int mb = 0; mb < 4; ++mb) {
        #pragma unroll
        for (int j = 0; j < 4; ++j) {
            int row = m0 + wm0 + mb * 16 + r_lo;
            int col = n0 + wn0 + j * 8 + c_off;
            float* C = acc[mb][j];
            #pragma unroll
            for (int h = 0; h < 2; ++h) {
                int rr = row + h * 8;
                float bz = g_zb[rr];
                float v0 = C[h * 2 + 0] + bz;
                float v1 = C[h * 2 + 1] + bz;
                bf16 h0, l0, h1, l1;
                split_bf16(v0, h0, l0);
                split_bf16(v1, h1, l1);
                size_t idx = base + (size_t)rr * Nn + col;
                *(uint32_t*)(g_z_h + idx) = pack2(h0, h1);
                *(uint32_t*)(g_z_l + idx) = pack2(l0, l1);
            }
        }
    }
}

// out[i][o] = elu(att @ z^T + fc_b) : M=1024(i), N=256(o), K=1024
__global__ __launch_bounds__(256) void out_mma(const float* __restrict__ bias,
                                               float* __restrict__ outF) {
    const int K = Nn;
    int b  = blockIdx.z;
    int m0 = blockIdx.y * 128;
    int n0 = blockIdx.x * 128;
    const bf16* Ah = g_att_h + (size_t)b * Nn * Nn;
    const bf16* Al = g_att_l + (size_t)b * Nn * Nn;
    const bf16* Bh = g_z_h + (size_t)b * OUTc * Nn;
    const bf16* Bl = g_z_l + (size_t)b * OUTc * Nn;

    __shared__ __align__(16) bf16 sAh[2 * 128 * SROW], sAl[2 * 128 * SROW];
    __shared__ __align__(16) bf16 sBh[2 * 128 * SROW], sBl[2 * 128 * SROW];

    int t = threadIdx.x;
    int lrow = t >> 1, lhalf = t & 1;
    const bf16* pAh = Ah + (size_t)(m0 + lrow) * K + lhalf * 8;
    const bf16* pAl = Al + (size_t)(m0 + lrow) * K + lhalf * 8;
    const bf16* pBh = Bh + (size_t)(n0 + lrow) * K + lhalf * 8;
    const bf16* pBl = Bl + (size_t)(n0 + lrow) * K + lhalf * 8;
    int sidx = lrow * 3 + lhalf;

    int wid = t >> 5, lane = t & 31;
    int wm0 = (wid >> 2) * 64;
    int wn0 = (wid & 3) * 32;
    int lr = lane & 15, lc = (lane >> 4) * 8;

    uint32_t saAh = (uint32_t)__cvta_generic_to_shared(sAh);
    uint32_t saAl = (uint32_t)__cvta_generic_to_shared(sAl);
    uint32_t saBh = (uint32_t)__cvta_generic_to_shared(sBh);
    uint32_t saBl = (uint32_t)__cvta_generic_to_shared(sBl);
    uint32_t aAddrH[4], aAddrL[4], bAddrH[2], bAddrL[2];
    #pragma unroll
    for (int mb = 0; mb < 4; ++mb) {
        uint32_t off = (uint32_t)((wm0 + mb * 16 + lr) * SROW + lc) * 2;
        aAddrH[mb] = saAh + off;
        aAddrL[mb] = saAl + off;
    }
    #pragma unroll
    for (int g = 0; g < 2; ++g) {
        uint32_t off = (uint32_t)((wn0 + g * 16 + lr) * SROW + lc) * 2;
        bAddrH[g] = saBh + off;
        bAddrL[g] = saBl + off;
    }

    float acc[4][4][4];
    #pragma unroll
    for (int i = 0; i < 4; ++i)
        #pragma unroll
        for (int j = 0; j < 4; ++j)
            #pragma unroll
            for (int q = 0; q < 4; ++q) acc[i][j][q] = 0.f;

    uint4 fa  = *(const uint4*)pAh;
    uint4 fb  = *(const uint4*)pAl;
    uint4 fc4 = *(const uint4*)pBh;
    uint4 fd  = *(const uint4*)pBl;
    ((uint4*)sAh)[sidx] = fa;
    ((uint4*)sAl)[sidx] = fb;
    ((uint4*)sBh)[sidx] = fc4;
    ((uint4*)sBl)[sidx] = fd;
    __syncthreads();

    uint32_t Afh[4][4], Afl[4][4], Bfh[2][4], Bfl[2][4];
    int cur = 0;

    for (int k0 = 0; k0 < K; k0 += 16) {
        bool has_next = (k0 + 16 < K);
        if (has_next) {
            fa  = *(const uint4*)(pAh + k0 + 16);
            fb  = *(const uint4*)(pAl + k0 + 16);
            fc4 = *(const uint4*)(pBh + k0 + 16);
            fd  = *(const uint4*)(pBl + k0 + 16);
        }
        uint32_t co = (uint32_t)cur * BUFB;
        #pragma unroll
        for (int mb = 0; mb < 4; ++mb) {
            ldsm4(Afh[mb][0], Afh[mb][1], Afh[mb][2], Afh[mb][3], aAddrH[mb] + co);
            ldsm4(Afl[mb][0], Afl[mb][1], Afl[mb][2], Afl[mb][3], aAddrL[mb] + co);
        }
        #pragma unroll
        for (int g = 0; g < 2; ++g) {
            ldsm4(Bfh[g][0], Bfh[g][1], Bfh[g][2], Bfh[g][3], bAddrH[g] + co);
            ldsm4(Bfl[g][0], Bfl[g][1], Bfl[g][2], Bfl[g][3], bAddrL[g] + co);
        }
        #pragma unroll
        for (int mb = 0; mb < 4; ++mb) {
            #pragma unroll
            for (int j = 0; j < 4; ++j) {
                int g = j >> 1, p = j & 1;
                float* C = acc[mb][j];
                mma16816(C[0], C[1], C[2], C[3],
                         Afh[mb][0], Afh[mb][1], Afh[mb][2], Afh[mb][3],
                         Bfh[g][p], Bfh[g][p + 2]);
                mma16816(C[0], C[1], C[2], C[3],
                         Afh[mb][0], Afh[mb][1], Afh[mb][2], Afh[mb][3],
                         Bfl[g][p], Bfl[g][p + 2]);
                mma16816(C[0], C[1], C[2], C[3],
                         Afl[mb][0], Afl[mb][1], Afl[mb][2], Afl[mb][3],
                         Bfh[g][p], Bfh[g][p + 2]);
            }
        }
        if (has_next) {
            int nidx = (cur ^ 1) * BUFU + sidx;
            ((uint4*)sAh)[nidx] = fa;
            ((uint4*)sAl)[nidx] = fb;
            ((uint4*)sBh)[nidx] = fc4;
            ((uint4*)sBl)[nidx] = fd;
        }
        __syncthreads();
        cur ^= 1;
    }

    int r_lo = lane >> 2, c_off = (lane & 3) * 2;
    size_t base = (size_t)b * Nn * OUTc;
    #pragma unroll
    for (int mb = 0; mb < 4; ++mb) {
        #pragma unroll
        for (int j = 0; j < 4; ++j) {
            int row = m0 + wm0 + mb * 16 + r_lo;
            int col = n0 + wn0 + j * 8 + c_off;
            float* C = acc[mb][j];
            #pragma unroll
            for (int h = 0; h < 2; ++h) {
                int rr = row + h * 8;
                float v0 = C[h * 2 + 0] + bias[col + 0];
                float v1 = C[h * 2 + 1] + bias[col + 1];
                v0 = v0 > 0.f ? v0 : (__expf(v0) - 1.f);
                v1 = v1 > 0.f ? v1 : (__expf(v1) - 1.f);
                *(float2*)(outF + base + (size_t)rr * OUTc + col) = make_float2(v0, v1);
            }
        }
    }
}

extern "C" void kernel_launch(void* const* d_in, const int* in_sizes, int n_in,
                              void* d_out, int out_size) {
    const float* x    = (const float*)d_in[0];
    const float* ax   = (const float*)d_in[1];
    const int*   adj  = (const int*)d_in[2];
    const float* WQ_w = (const float*)d_in[3];
    const float* WQ_b = (const float*)d_in[4];
    const float* a    = (const float*)d_in[5];
    const float* fc_w = (const float*)d_in[6];
    const float* fc_b = (const float*)d_in[7];
    float* out = (float*)d_out;

    prep_M<<<256, 256>>>(fc_w, WQ_w);
    prep_small<<<1, 256>>>(WQ_w, WQ_b, a, fc_w);
    conv_w<<<(OUTc * Dd) / 256, 256>>>(fc_w);

    dim3 cxg(Dd / 32, Nn / 32, Bb);
    conv_x<<<cxg, 256>>>(x, ax);

    dim3 fg(Nn / 32, Bb), fb(32, 8);
    f_kernel<<<fg, fb>>>(x, ax, a);

    dim3 ag(Nn, Bb);
    att_kernel<<<ag, 256>>>(adj);

    z_mma<<<dim3(Nn / 128, OUTc / 128, Bb), 256>>>();
    out_mma<<<dim3(OUTc / 128, Nn / 128, Bb), 256>>>(fc_b, out);
}